// round 1
// baseline (speedup 1.0000x reference)
#include <cuda_runtime.h>

// Problem constants
#define Bc   32
#define Tc   512
#define Hc   256
#define Lc   2048
#define NLc  4

static const int ROWS_DUR = Bc * Tc;   // 16384
static const int ROWS_MEL = Bc * Lc;   // 65536

// Scratch (device globals; no runtime allocation)
__device__ float          g_xe[Bc * Lc * Hc];   // length-regulated features [B,L,H]
__device__ int            g_idx[Bc * Lc];
__device__ unsigned char  g_mmask[Bc * Lc];     // 1 = padded frame

// ---- packed fp32x2 helpers ----
#define PACK2(dst, lo, hi)   asm("mov.b64 %0, {%1, %2};" : "=l"(dst) : "f"(lo), "f"(hi))
#define UNPACK2(lo, hi, src) asm("mov.b64 {%0, %1}, %2;" : "=f"(lo), "=f"(hi) : "l"(src))
#define FFMA2(acc, a, b)     asm("fma.rn.f32x2 %0, %1, %2, %0;" : "+l"(acc) : "l"(a), "l"(b))

// ============================================================
// Length regulator: cumsum + searchsorted + masks (1 block / batch)
// ============================================================
__global__ void regulate_kernel(const int* __restrict__ dur,
                                float* __restrict__ out_mellen,
                                float* __restrict__ out_melmask)
{
    __shared__ int cum[Tc];
    const int b = blockIdx.x;
    const int t = threadIdx.x;
    cum[t] = dur[b * Tc + t];
    __syncthreads();
    // inclusive scan
    for (int off = 1; off < Tc; off <<= 1) {
        int v = (t >= off) ? cum[t - off] : 0;
        __syncthreads();
        cum[t] += v;
        __syncthreads();
    }
    const int mel_len = min(cum[Tc - 1], Lc);
    for (int m = t; m < Lc; m += Tc) {
        // searchsorted(cum, m, 'right') = first i with cum[i] > m
        int lo = 0, hi = Tc;
        while (lo < hi) {
            int mid = (lo + hi) >> 1;
            if (cum[mid] <= m) lo = mid + 1; else hi = mid;
        }
        int idx = min(lo, Tc - 1);
        bool pad = (m >= mel_len);
        g_idx[b * Lc + m]      = idx;
        g_mmask[b * Lc + m]    = pad ? 1 : 0;
        out_melmask[b * Lc + m] = pad ? 1.0f : 0.0f;
    }
    if (t == 0) out_mellen[b] = (float)mel_len;
}

// ============================================================
// Gather: xe[b,l,:] = x[b, idx[b,l], :] * !pad
// ============================================================
__global__ void gather_kernel(const float* __restrict__ x)
{
    const int total4 = ROWS_MEL * (Hc / 4);
    int e4 = blockIdx.x * blockDim.x + threadIdx.x;
    if (e4 >= total4) return;
    int row = e4 / (Hc / 4);
    int h4  = e4 % (Hc / 4);
    int b   = row / Lc;
    int idx = g_idx[row];
    float4 v = ((const float4*)(x + ((size_t)b * Tc + idx) * Hc))[h4];
    if (g_mmask[row]) v = make_float4(0.f, 0.f, 0.f, 0.f);
    ((float4*)g_xe)[e4] = v;
}

// ============================================================
// Fused 4-layer MLP predictor + head.
// MODE 0: duration -> (tanh(d)+1)*src_seq[:,:,2]
// MODE 1: pitch    -> relu(head)
// MODE 2: energy   -> head
// 64 rows/block, 256 threads; each thread: 8 rows x 8 cols, f32x2 packed.
// ============================================================
template <int MODE>
__global__ void __launch_bounds__(256, 1)
predictor_kernel(const float* __restrict__ Xin,             // null -> g_xe
                 const float* __restrict__ W,               // [NL,H,H]
                 const float* __restrict__ Bv,              // [NL,H]
                 const float* __restrict__ wHead,           // [H]
                 const float* __restrict__ b2,               // [1]
                 const unsigned char* __restrict__ maskIn,   // null -> g_mmask
                 const float* __restrict__ src_seq,          // MODE0 only
                 float* __restrict__ out)                    // [R]
{
    const float* X = Xin ? Xin : g_xe;
    const unsigned char* mask = maskIn ? maskIn : g_mmask;

    extern __shared__ float sm[];
    float* hA = sm;
    float* hB = sm + 64 * Hc;

    const int tid = threadIdx.x;
    const int tx  = tid & 31;   // column group: cols [tx*8, tx*8+8)
    const int ty  = tid >> 5;   // row group: rows ty, ty+8, ..., ty+56
    const int r0  = blockIdx.x * 64;

    // Load input tile (64 x 256) into hA
    {
        const float4* Xv = (const float4*)(X + (size_t)r0 * Hc);
        float4* dst = (float4*)hA;
        #pragma unroll
        for (int i = 0; i < 16; i++) dst[tid + 256 * i] = Xv[tid + 256 * i];
    }
    __syncthreads();

    float* hin  = hA;
    float* hout = hB;

    #pragma unroll 1
    for (int l = 0; l < NLc; l++) {
        const float* Wl = W + l * Hc * Hc + tx * 8;
        const float* bl = Bv + l * Hc + tx * 8;

        unsigned long long acc[8][4];
        {
            unsigned long long bp[4];
            #pragma unroll
            for (int c = 0; c < 4; c++) PACK2(bp[c], bl[2 * c], bl[2 * c + 1]);
            #pragma unroll
            for (int ri = 0; ri < 8; ri++)
                #pragma unroll
                for (int c = 0; c < 4; c++) acc[ri][c] = bp[c];
        }

        #pragma unroll 4
        for (int k = 0; k < Hc; k++) {
            const float4 w0 = *(const float4*)(Wl + k * Hc);
            const float4 w1 = *(const float4*)(Wl + k * Hc + 4);
            unsigned long long wp[4];
            PACK2(wp[0], w0.x, w0.y);
            PACK2(wp[1], w0.z, w0.w);
            PACK2(wp[2], w1.x, w1.y);
            PACK2(wp[3], w1.z, w1.w);
            #pragma unroll
            for (int ri = 0; ri < 8; ri++) {
                float hv = hin[(ty + ri * 8) * Hc + k];
                unsigned long long hp;
                PACK2(hp, hv, hv);
                #pragma unroll
                for (int c = 0; c < 4; c++) FFMA2(acc[ri][c], hp, wp[c]);
            }
        }

        // relu + write to hout
        #pragma unroll
        for (int ri = 0; ri < 8; ri++) {
            float4 v0, v1;
            UNPACK2(v0.x, v0.y, acc[ri][0]);
            UNPACK2(v0.z, v0.w, acc[ri][1]);
            UNPACK2(v1.x, v1.y, acc[ri][2]);
            UNPACK2(v1.z, v1.w, acc[ri][3]);
            v0.x = fmaxf(v0.x, 0.f); v0.y = fmaxf(v0.y, 0.f);
            v0.z = fmaxf(v0.z, 0.f); v0.w = fmaxf(v0.w, 0.f);
            v1.x = fmaxf(v1.x, 0.f); v1.y = fmaxf(v1.y, 0.f);
            v1.z = fmaxf(v1.z, 0.f); v1.w = fmaxf(v1.w, 0.f);
            float* dst = hout + (ty + ri * 8) * Hc + tx * 8;
            *(float4*)dst       = v0;
            *(float4*)(dst + 4) = v1;
        }
        __syncthreads();
        float* tmp = hin; hin = hout; hout = tmp;
    }

    // Head: out[r] = dot(h[r], wHead) + b2, then mask + epilogue.
    hout[tid] = wHead[tid];   // hout no longer holds live data
    __syncthreads();

    const int row  = tid >> 2;   // 0..63
    const int part = tid & 3;
    const float* hr = hin + row * Hc + part * 64;
    const float* wr = hout + part * 64;
    float s = 0.f;
    #pragma unroll
    for (int k = 0; k < 64; k++) s += hr[k] * wr[k];
    s += __shfl_xor_sync(0xffffffffu, s, 1);
    s += __shfl_xor_sync(0xffffffffu, s, 2);

    if (part == 0) {
        const int r = r0 + row;
        float val = s + b2[0];
        if (mask[r]) val = 0.f;
        float res;
        if (MODE == 0)      res = (tanhf(val) + 1.f) * src_seq[r * 3 + 2];
        else if (MODE == 1) res = fmaxf(val, 0.f);
        else                res = val;
        out[r] = res;
    }
}

// ============================================================
// Final: out = xe + pitch_emb[ceil(p*NB)] + energy_emb[ceil(e*NB)]
// ============================================================
__global__ void final_kernel(const float* __restrict__ pitch_t,
                             const float* __restrict__ energy_t,
                             const float* __restrict__ pemb,
                             const float* __restrict__ eemb,
                             float* __restrict__ out)
{
    const int total4 = ROWS_MEL * (Hc / 4);
    int e4 = blockIdx.x * blockDim.x + threadIdx.x;
    if (e4 >= total4) return;
    int row = e4 / (Hc / 4);
    int h4  = e4 % (Hc / 4);
    int pi = (int)ceilf(pitch_t[row] * 256.0f);
    int ei = (int)ceilf(energy_t[row] * 256.0f);
    float4 a = ((const float4*)g_xe)[e4];
    float4 p = ((const float4*)(pemb + (size_t)pi * Hc))[h4];
    float4 q = ((const float4*)(eemb + (size_t)ei * Hc))[h4];
    a.x += p.x + q.x;
    a.y += p.y + q.y;
    a.z += p.z + q.z;
    a.w += p.w + q.w;
    ((float4*)out)[e4] = a;
}

// ============================================================
extern "C" void kernel_launch(void* const* d_in, const int* in_sizes, int n_in,
                              void* d_out, int out_size)
{
    const float* x        = (const float*)d_in[0];   // [B,T,H]
    const float* src_seq  = (const float*)d_in[1];   // [B,T,3]
    const int*   dur_t    = (const int*)  d_in[2];   // [B,T]
    const float* pitch_t  = (const float*)d_in[3];   // [B,L]
    const float* energy_t = (const float*)d_in[4];   // [B,L]
    const unsigned char* src_mask = (const unsigned char*)d_in[5]; // [B,T] bool

    // Weights are the last 14 inputs (robust to whether max_len scalar is passed)
    const int base = n_in - 14;
    const float* dur_W  = (const float*)d_in[base + 0];
    const float* dur_b  = (const float*)d_in[base + 1];
    const float* dur_w  = (const float*)d_in[base + 2];
    const float* dur_b2 = (const float*)d_in[base + 3];
    const float* pit_W  = (const float*)d_in[base + 4];
    const float* pit_b  = (const float*)d_in[base + 5];
    const float* pit_w  = (const float*)d_in[base + 6];
    const float* pit_b2 = (const float*)d_in[base + 7];
    const float* en_W   = (const float*)d_in[base + 8];
    const float* en_b   = (const float*)d_in[base + 9];
    const float* en_w   = (const float*)d_in[base + 10];
    const float* en_b2  = (const float*)d_in[base + 11];
    const float* pemb   = (const float*)d_in[base + 12];
    const float* eemb   = (const float*)d_in[base + 13];

    float* out       = (float*)d_out;
    float* o_main    = out;                               // B*L*H
    float* o_logdur  = o_main + (size_t)ROWS_MEL * Hc;    // B*T
    float* o_pitch   = o_logdur + ROWS_DUR;               // B*L
    float* o_energy  = o_pitch + ROWS_MEL;                // B*L
    float* o_mellen  = o_energy + ROWS_MEL;               // B
    float* o_mmask   = o_mellen + Bc;                     // B*L

    const size_t smem = 2 * 64 * Hc * sizeof(float);      // 128 KB
    cudaFuncSetAttribute(predictor_kernel<0>, cudaFuncAttributeMaxDynamicSharedMemorySize, (int)smem);
    cudaFuncSetAttribute(predictor_kernel<1>, cudaFuncAttributeMaxDynamicSharedMemorySize, (int)smem);
    cudaFuncSetAttribute(predictor_kernel<2>, cudaFuncAttributeMaxDynamicSharedMemorySize, (int)smem);

    // 1) length regulator metadata (mel_len, mel_mask, gather indices)
    regulate_kernel<<<Bc, Tc>>>(dur_t, o_mellen, o_mmask);

    // 2) materialize xe
    const int total4 = ROWS_MEL * (Hc / 4);
    gather_kernel<<<(total4 + 255) / 256, 256>>>(x);

    // 3) three predictors
    predictor_kernel<0><<<ROWS_DUR / 64, 256, smem>>>(
        x, dur_W, dur_b, dur_w, dur_b2, src_mask, src_seq, o_logdur);
    predictor_kernel<1><<<ROWS_MEL / 64, 256, smem>>>(
        nullptr, pit_W, pit_b, pit_w, pit_b2, nullptr, nullptr, o_pitch);
    predictor_kernel<2><<<ROWS_MEL / 64, 256, smem>>>(
        nullptr, en_W, en_b, en_w, en_b2, nullptr, nullptr, o_energy);

    // 4) out = xe + pitch_emb + energy_emb
    final_kernel<<<(total4 + 255) / 256, 256>>>(pitch_t, energy_t, pemb, eemb, o_main);
}

// round 3
// speedup vs baseline: 2.8751x; 2.8751x over previous
#include <cuda_runtime.h>
#include <cuda_bf16.h>
#include <cstdint>

// Problem constants
#define Bc   32
#define Tc   512
#define Hc   256
#define Lc   2048
#define NLc  4

static const int ROWS_DUR = Bc * Tc;   // 16384
static const int ROWS_MEL = Bc * Lc;   // 65536
static const int N_PIT_TILES = ROWS_MEL / 128;   // 512
static const int N_DUR_TILES = ROWS_DUR / 128;   // 128

// Scratch (device globals; no runtime allocation)
__device__ float          g_xe[Bc * Lc * Hc];   // length-regulated features [B,L,H]
__device__ int            g_idx[Bc * Lc];
__device__ unsigned char  g_mmask[Bc * Lc];     // 1 = padded frame
// Fragment-order weight blob: [pred(3)][layer(4)][kstep(16)][nsub(32)][lane(32)] x uint4
// uint4 = {b0_hi, b1_hi, b0_lo, b1_lo} (bf16x2 each) for mma.m16n8k16 col-major B frags
__device__ __align__(128) uint4 g_wblob[3 * 4 * 16 * 32 * 32];

__device__ __forceinline__ uint32_t smem_u32(const void* p) {
    uint32_t a;
    asm("{ .reg .u64 t; cvta.to.shared.u64 t, %1; cvt.u32.u64 %0, t; }" : "=r"(a) : "l"(p));
    return a;
}
__device__ __forceinline__ uint32_t pack_bf16x2(float a, float b) {
    __nv_bfloat162 t = __floats2bfloat162_rn(a, b);
    return *reinterpret_cast<uint32_t*>(&t);
}
__device__ __forceinline__ void mma16816(float* c, const uint32_t* a, uint32_t b0, uint32_t b1) {
    asm volatile(
        "mma.sync.aligned.m16n8k16.row.col.f32.bf16.bf16.f32 "
        "{%0,%1,%2,%3}, {%4,%5,%6,%7}, {%8,%9}, {%0,%1,%2,%3};"
        : "+f"(c[0]), "+f"(c[1]), "+f"(c[2]), "+f"(c[3])
        : "r"(a[0]), "r"(a[1]), "r"(a[2]), "r"(a[3]), "r"(b0), "r"(b1));
}
__device__ __forceinline__ void cp16(void* dst_smem, const void* src) {
    uint32_t d = smem_u32(dst_smem);
    asm volatile("cp.async.cg.shared.global [%0], [%1], 16;" :: "r"(d), "l"(src) : "memory");
}
#define CP_COMMIT() asm volatile("cp.async.commit_group;" ::: "memory")
#define CP_WAIT(N)  asm volatile("cp.async.wait_group %0;" :: "n"(N) : "memory")

// ============================================================
// Weight prep: fp32 W[k][n] -> bf16 hi/lo mma fragments in blob order.
// ============================================================
__global__ void prep_kernel(const float* __restrict__ durW,
                            const float* __restrict__ pitW,
                            const float* __restrict__ enW)
{
    int i = blockIdx.x * 256 + threadIdx.x;   // 196608 total
    int lane  = i & 31;
    int nsub  = (i >> 5) & 31;
    int kstep = (i >> 10) & 15;
    int l     = (i >> 14) & 3;
    int p     = i >> 16;                      // 0..2
    const float* W = (p == 0 ? durW : (p == 1 ? pitW : enW)) + l * Hc * Hc;
    int n  = nsub * 8 + (lane >> 2);
    int tg = lane & 3;
    int kA = kstep * 16 + tg * 2;
    int kB = kA + 8;
    float w00 = W[kA * Hc + n],       w01 = W[(kA + 1) * Hc + n];
    float w10 = W[kB * Hc + n],       w11 = W[(kB + 1) * Hc + n];
    float h00 = __bfloat162float(__float2bfloat16(w00));
    float h01 = __bfloat162float(__float2bfloat16(w01));
    float h10 = __bfloat162float(__float2bfloat16(w10));
    float h11 = __bfloat162float(__float2bfloat16(w11));
    uint4 v;
    v.x = pack_bf16x2(h00, h01);
    v.y = pack_bf16x2(h10, h11);
    v.z = pack_bf16x2(w00 - h00, w01 - h01);
    v.w = pack_bf16x2(w10 - h10, w11 - h11);
    g_wblob[i] = v;
}

// ============================================================
// Length regulator: cumsum + searchsorted + masks (1 block / batch)
// ============================================================
__global__ void regulate_kernel(const int* __restrict__ dur,
                                float* __restrict__ out_mellen,
                                float* __restrict__ out_melmask)
{
    __shared__ int cum[Tc];
    const int b = blockIdx.x;
    const int t = threadIdx.x;
    cum[t] = dur[b * Tc + t];
    __syncthreads();
    for (int off = 1; off < Tc; off <<= 1) {
        int v = (t >= off) ? cum[t - off] : 0;
        __syncthreads();
        cum[t] += v;
        __syncthreads();
    }
    const int mel_len = min(cum[Tc - 1], Lc);
    for (int m = t; m < Lc; m += Tc) {
        int lo = 0, hi = Tc;
        while (lo < hi) {
            int mid = (lo + hi) >> 1;
            if (cum[mid] <= m) lo = mid + 1; else hi = mid;
        }
        int idx = min(lo, Tc - 1);
        bool pad = (m >= mel_len);
        g_idx[b * Lc + m]       = idx;
        g_mmask[b * Lc + m]     = pad ? 1 : 0;
        out_melmask[b * Lc + m] = pad ? 1.0f : 0.0f;
    }
    if (t == 0) out_mellen[b] = (float)mel_len;
}

// ============================================================
// Gather: xe[b,l,:] = x[b, idx[b,l], :] * !pad
// ============================================================
__global__ void gather_kernel(const float* __restrict__ x)
{
    const int total4 = ROWS_MEL * (Hc / 4);
    int e4 = blockIdx.x * blockDim.x + threadIdx.x;
    if (e4 >= total4) return;
    int row = e4 / (Hc / 4);
    int h4  = e4 % (Hc / 4);
    int b   = row / Lc;
    int idx = g_idx[row];
    float4 v = ((const float4*)(x + ((size_t)b * Tc + idx) * Hc))[h4];
    if (g_mmask[row]) v = make_float4(0.f, 0.f, 0.f, 0.f);
    ((float4*)g_xe)[e4] = v;
}

// ============================================================
// mma.sync predictor. 512 threads = 16 warps (4M x 4N), tile 128x256.
// SMEM: h_hi/h_lo activations (pitch 264), 2x32KB B double-buffer, bias, head.
// ============================================================
#define PITCH 264
#define OFF_HHI   0
#define OFF_HLO   (128 * PITCH * 2)                 // 67584
#define OFF_BBUF  (OFF_HLO + 128 * PITCH * 2)       // 135168
#define OFF_BIAS  (OFF_BBUF + 2 * 32768)            // 200704
#define OFF_WHEAD (OFF_BIAS + 4 * 256 * 4)          // 204800
#define OFF_HEAD  (OFF_WHEAD + 256 * 4)             // 205824
#define SMEM_TOTAL (OFF_HEAD + 128 * 4)             // 206336

__global__ void __launch_bounds__(512, 1)
predictor_mma(const float* __restrict__ x,
              const float* __restrict__ src_seq,
              const unsigned char* __restrict__ src_mask,
              const float* __restrict__ dur_b, const float* __restrict__ pit_b,
              const float* __restrict__ en_b,
              const float* __restrict__ dur_w, const float* __restrict__ pit_w,
              const float* __restrict__ en_w,
              const float* __restrict__ dur_b2, const float* __restrict__ pit_b2,
              const float* __restrict__ en_b2,
              float* __restrict__ o_logdur, float* __restrict__ o_pitch,
              float* __restrict__ o_energy)
{
    extern __shared__ char smem[];
    __nv_bfloat16* h_hi = (__nv_bfloat16*)(smem + OFF_HHI);
    __nv_bfloat16* h_lo = (__nv_bfloat16*)(smem + OFF_HLO);
    char*          bbuf = smem + OFF_BBUF;
    float*         bias_s  = (float*)(smem + OFF_BIAS);
    float*         whead_s = (float*)(smem + OFF_WHEAD);
    float*         headsum = (float*)(smem + OFF_HEAD);

    const int tid  = threadIdx.x;
    const int lane = tid & 31;
    const int wid  = tid >> 5;
    const int warpM = wid >> 2;          // 0..3 (32 rows each)
    const int warpN = wid & 3;           // 0..3 (64 cols each)
    const int g  = lane >> 2;
    const int tg = lane & 3;
    const int bid = blockIdx.x;

    int pred;
    long r0;
    const float* X;
    const float* bias;
    const float* wh;
    const float* b2;
    float* out;
    if (bid < N_PIT_TILES) {
        pred = 1; r0 = (long)bid * 128; X = g_xe;
        bias = pit_b; wh = pit_w; b2 = pit_b2; out = o_pitch;
    } else if (bid < 2 * N_PIT_TILES) {
        pred = 2; r0 = (long)(bid - N_PIT_TILES) * 128; X = g_xe;
        bias = en_b; wh = en_w; b2 = en_b2; out = o_energy;
    } else {
        pred = 0; r0 = (long)(bid - 2 * N_PIT_TILES) * 128; X = x;
        bias = dur_b; wh = dur_w; b2 = dur_b2; out = o_logdur;
    }
    const char* blob = (const char*)g_wblob + (size_t)pred * 4 * 262144;

    // prefetch chunk 0 (ksteps 0,1 of layer 0): 32KB, 64B per thread
    {
        const char* src = blob + (size_t)tid * 64;
        char* dst = bbuf + tid * 64;
        #pragma unroll
        for (int q = 0; q < 4; q++) cp16(dst + q * 16, src + q * 16);
        CP_COMMIT();
    }

    // bias + head weights + headsum init
    for (int i = tid; i < NLc * Hc; i += 512) bias_s[i] = bias[i];
    for (int i = tid; i < Hc; i += 512) whead_s[i] = wh[i];
    if (tid < 128) headsum[tid] = 0.f;

    // A init: split fp32 input -> bf16 hi/lo in SMEM
    {
        const int row = tid >> 2;
        const int c0  = (tid & 3) * 64;
        const float* xr = X + (r0 + row) * (long)Hc + c0;
        __nv_bfloat16* dh = h_hi + row * PITCH + c0;
        __nv_bfloat16* dl = h_lo + row * PITCH + c0;
        #pragma unroll
        for (int q = 0; q < 16; q++) {
            float4 v = ((const float4*)xr)[q];
            float a0 = __bfloat162float(__float2bfloat16(v.x));
            float a1 = __bfloat162float(__float2bfloat16(v.y));
            float a2 = __bfloat162float(__float2bfloat16(v.z));
            float a3 = __bfloat162float(__float2bfloat16(v.w));
            *(uint32_t*)(dh + q * 4)     = pack_bf16x2(a0, a1);
            *(uint32_t*)(dh + q * 4 + 2) = pack_bf16x2(a2, a3);
            *(uint32_t*)(dl + q * 4)     = pack_bf16x2(v.x - a0, v.y - a1);
            *(uint32_t*)(dl + q * 4 + 2) = pack_bf16x2(v.z - a2, v.w - a3);
        }
    }
    __syncthreads();

    float acc[2][8][4];
    #pragma unroll
    for (int m = 0; m < 2; m++)
        #pragma unroll
        for (int j = 0; j < 8; j++)
            #pragma unroll
            for (int q = 0; q < 4; q++) acc[m][j][q] = 0.f;

    float hp[4] = {0.f, 0.f, 0.f, 0.f};   // head partials (msub x row-pair)

    #pragma unroll 1
    for (int l = 0; l < NLc; l++) {
        #pragma unroll 1
        for (int c = 0; c < 8; c++) {
            const int gch = l * 8 + c;
            if (gch + 1 < 32) {
                const char* src = blob + (size_t)(gch + 1) * 32768 + (size_t)tid * 64;
                char* dst = bbuf + ((gch + 1) & 1) * 32768 + tid * 64;
                #pragma unroll
                for (int q = 0; q < 4; q++) cp16(dst + q * 16, src + q * 16);
                CP_COMMIT();
                CP_WAIT(1);
            } else {
                CP_WAIT(0);
            }
            __syncthreads();

            const char* bb = bbuf + (gch & 1) * 32768;
            #pragma unroll
            for (int ksIn = 0; ksIn < 2; ksIn++) {
                const int k0 = (c * 2 + ksIn) * 16;
                uint32_t ahi[2][4], alo[2][4];
                #pragma unroll
                for (int m = 0; m < 2; m++) {
                    const int rr = warpM * 32 + m * 16 + g;
                    const int ka = k0 + tg * 2;
                    ahi[m][0] = *(const uint32_t*)(h_hi + rr * PITCH + ka);
                    ahi[m][1] = *(const uint32_t*)(h_hi + (rr + 8) * PITCH + ka);
                    ahi[m][2] = *(const uint32_t*)(h_hi + rr * PITCH + ka + 8);
                    ahi[m][3] = *(const uint32_t*)(h_hi + (rr + 8) * PITCH + ka + 8);
                    alo[m][0] = *(const uint32_t*)(h_lo + rr * PITCH + ka);
                    alo[m][1] = *(const uint32_t*)(h_lo + (rr + 8) * PITCH + ka);
                    alo[m][2] = *(const uint32_t*)(h_lo + rr * PITCH + ka + 8);
                    alo[m][3] = *(const uint32_t*)(h_lo + (rr + 8) * PITCH + ka + 8);
                }
                #pragma unroll
                for (int j = 0; j < 8; j++) {
                    const uint4 B = *(const uint4*)(bb +
                        ((size_t)(ksIn * 32 + warpN * 8 + j) * 32 + lane) * 16);
                    #pragma unroll
                    for (int m = 0; m < 2; m++) {
                        mma16816(acc[m][j], ahi[m], B.x, B.y);   // Ahi*Bhi
                        mma16816(acc[m][j], ahi[m], B.z, B.w);   // Ahi*Blo
                        mma16816(acc[m][j], alo[m], B.x, B.y);   // Alo*Bhi
                    }
                }
            }
            __syncthreads();
        }

        // ---- layer epilogue ----
        const float* bl = bias_s + l * Hc;
        if (l < NLc - 1) {
            #pragma unroll
            for (int m = 0; m < 2; m++) {
                const int rr = warpM * 32 + m * 16 + g;
                #pragma unroll
                for (int j = 0; j < 8; j++) {
                    const int col = warpN * 64 + j * 8 + tg * 2;
                    float v0 = fmaxf(acc[m][j][0] + bl[col],     0.f);
                    float v1 = fmaxf(acc[m][j][1] + bl[col + 1], 0.f);
                    float v2 = fmaxf(acc[m][j][2] + bl[col],     0.f);
                    float v3 = fmaxf(acc[m][j][3] + bl[col + 1], 0.f);
                    float h0 = __bfloat162float(__float2bfloat16(v0));
                    float h1 = __bfloat162float(__float2bfloat16(v1));
                    float h2 = __bfloat162float(__float2bfloat16(v2));
                    float h3 = __bfloat162float(__float2bfloat16(v3));
                    *(uint32_t*)(h_hi + rr * PITCH + col)       = pack_bf16x2(h0, h1);
                    *(uint32_t*)(h_hi + (rr + 8) * PITCH + col) = pack_bf16x2(h2, h3);
                    *(uint32_t*)(h_lo + rr * PITCH + col)       = pack_bf16x2(v0 - h0, v1 - h1);
                    *(uint32_t*)(h_lo + (rr + 8) * PITCH + col) = pack_bf16x2(v2 - h2, v3 - h3);
                    acc[m][j][0] = 0.f; acc[m][j][1] = 0.f;
                    acc[m][j][2] = 0.f; acc[m][j][3] = 0.f;
                }
            }
            __syncthreads();
        } else {
            #pragma unroll
            for (int m = 0; m < 2; m++) {
                #pragma unroll
                for (int j = 0; j < 8; j++) {
                    const int col = warpN * 64 + j * 8 + tg * 2;
                    float w0 = whead_s[col], w1 = whead_s[col + 1];
                    hp[m * 2]     += fmaxf(acc[m][j][0] + bl[col],     0.f) * w0
                                   + fmaxf(acc[m][j][1] + bl[col + 1], 0.f) * w1;
                    hp[m * 2 + 1] += fmaxf(acc[m][j][2] + bl[col],     0.f) * w0
                                   + fmaxf(acc[m][j][3] + bl[col + 1], 0.f) * w1;
                }
            }
        }
    }

    // head reduction: atomicAdd into per-row shared slots
    #pragma unroll
    for (int m = 0; m < 2; m++) {
        const int rr = warpM * 32 + m * 16 + g;
        atomicAdd(&headsum[rr],     hp[m * 2]);
        atomicAdd(&headsum[rr + 8], hp[m * 2 + 1]);
    }
    __syncthreads();

    if (tid < 128) {
        const long r = r0 + tid;
        float val = headsum[tid] + b2[0];
        const bool msk = (pred == 0) ? (src_mask[r] != 0) : (g_mmask[r] != 0);
        if (msk) val = 0.f;
        float res;
        if (pred == 0)      res = (tanhf(val) + 1.f) * src_seq[r * 3 + 2];
        else if (pred == 1) res = fmaxf(val, 0.f);
        else                res = val;
        out[r] = res;
    }
}

// ============================================================
// Final: out = xe + pitch_emb[ceil(p*NB)] + energy_emb[ceil(e*NB)]
// ============================================================
__global__ void final_kernel(const float* __restrict__ pitch_t,
                             const float* __restrict__ energy_t,
                             const float* __restrict__ pemb,
                             const float* __restrict__ eemb,
                             float* __restrict__ out)
{
    const int total4 = ROWS_MEL * (Hc / 4);
    int e4 = blockIdx.x * blockDim.x + threadIdx.x;
    if (e4 >= total4) return;
    int row = e4 / (Hc / 4);
    int h4  = e4 % (Hc / 4);
    int pi = (int)ceilf(pitch_t[row] * 256.0f);
    int ei = (int)ceilf(energy_t[row] * 256.0f);
    float4 a = ((const float4*)g_xe)[e4];
    float4 p = ((const float4*)(pemb + (size_t)pi * Hc))[h4];
    float4 q = ((const float4*)(eemb + (size_t)ei * Hc))[h4];
    a.x += p.x + q.x;
    a.y += p.y + q.y;
    a.z += p.z + q.z;
    a.w += p.w + q.w;
    ((float4*)out)[e4] = a;
}

// ============================================================
extern "C" void kernel_launch(void* const* d_in, const int* in_sizes, int n_in,
                              void* d_out, int out_size)
{
    const float* x        = (const float*)d_in[0];   // [B,T,H]
    const float* src_seq  = (const float*)d_in[1];   // [B,T,3]
    const int*   dur_t    = (const int*)  d_in[2];   // [B,T]
    const float* pitch_t  = (const float*)d_in[3];   // [B,L]
    const float* energy_t = (const float*)d_in[4];   // [B,L]
    const unsigned char* src_mask = (const unsigned char*)d_in[5]; // [B,T] bool

    const int base = n_in - 14;
    const float* dur_W  = (const float*)d_in[base + 0];
    const float* dur_b  = (const float*)d_in[base + 1];
    const float* dur_w  = (const float*)d_in[base + 2];
    const float* dur_b2 = (const float*)d_in[base + 3];
    const float* pit_W  = (const float*)d_in[base + 4];
    const float* pit_b  = (const float*)d_in[base + 5];
    const float* pit_w  = (const float*)d_in[base + 6];
    const float* pit_b2 = (const float*)d_in[base + 7];
    const float* en_W   = (const float*)d_in[base + 8];
    const float* en_b   = (const float*)d_in[base + 9];
    const float* en_w   = (const float*)d_in[base + 10];
    const float* en_b2  = (const float*)d_in[base + 11];
    const float* pemb   = (const float*)d_in[base + 12];
    const float* eemb   = (const float*)d_in[base + 13];

    float* out       = (float*)d_out;
    float* o_main    = out;                               // B*L*H
    float* o_logdur  = o_main + (size_t)ROWS_MEL * Hc;    // B*T
    float* o_pitch   = o_logdur + ROWS_DUR;               // B*L
    float* o_energy  = o_pitch + ROWS_MEL;                // B*L
    float* o_mellen  = o_energy + ROWS_MEL;               // B
    float* o_mmask   = o_mellen + Bc;                     // B*L

    cudaFuncSetAttribute(predictor_mma, cudaFuncAttributeMaxDynamicSharedMemorySize, SMEM_TOTAL);

    // 0) build fragment-order weight blob
    prep_kernel<<<768, 256>>>(dur_W, pit_W, en_W);

    // 1) length regulator metadata
    regulate_kernel<<<Bc, Tc>>>(dur_t, o_mellen, o_mmask);

    // 2) materialize xe
    const int total4 = ROWS_MEL * (Hc / 4);
    gather_kernel<<<(total4 + 255) / 256, 256>>>(x);

    // 3) all three predictors in one mma.sync kernel
    predictor_mma<<<2 * N_PIT_TILES + N_DUR_TILES, 512, SMEM_TOTAL>>>(
        x, src_seq, src_mask,
        dur_b, pit_b, en_b, dur_w, pit_w, en_w, dur_b2, pit_b2, en_b2,
        o_logdur, o_pitch, o_energy);

    // 4) out = xe + pitch_emb + energy_emb
    final_kernel<<<(total4 + 255) / 256, 256>>>(pitch_t, energy_t, pemb, eemb, o_main);
}

// round 4
// speedup vs baseline: 3.2716x; 1.1379x over previous
#include <cuda_runtime.h>
#include <cuda_bf16.h>
#include <cstdint>

// Problem constants
#define Bc   32
#define Tc   512
#define Hc   256
#define Lc   2048
#define NLc  4

static const int ROWS_DUR = Bc * Tc;   // 16384
static const int ROWS_MEL = Bc * Lc;   // 65536
static const int N_PIT_TILES = ROWS_MEL / 64;   // 1024
static const int N_DUR_TILES = ROWS_DUR / 64;   // 256

// Scratch (device globals; no runtime allocation)
__device__ int            g_idx[Bc * Lc];
__device__ unsigned char  g_mmask[Bc * Lc];     // 1 = padded frame
// Fragment-order weight blob: [pred(3)][layer(4)][kstep(16)][nsub(32)][lane(32)] x uint4
// uint4 = {b0_hi, b1_hi, b0_lo, b1_lo} (bf16x2 each) for mma.m16n8k16 col-major B frags
__device__ __align__(128) uint4 g_wblob[3 * 4 * 16 * 32 * 32];

__device__ __forceinline__ uint32_t smem_u32(const void* p) {
    uint32_t a;
    asm("{ .reg .u64 t; cvta.to.shared.u64 t, %1; cvt.u32.u64 %0, t; }" : "=r"(a) : "l"(p));
    return a;
}
__device__ __forceinline__ uint32_t pack_bf16x2(float a, float b) {
    __nv_bfloat162 t = __floats2bfloat162_rn(a, b);
    return *reinterpret_cast<uint32_t*>(&t);
}
__device__ __forceinline__ void mma16816(float* c, const uint32_t* a, uint32_t b0, uint32_t b1) {
    asm volatile(
        "mma.sync.aligned.m16n8k16.row.col.f32.bf16.bf16.f32 "
        "{%0,%1,%2,%3}, {%4,%5,%6,%7}, {%8,%9}, {%0,%1,%2,%3};"
        : "+f"(c[0]), "+f"(c[1]), "+f"(c[2]), "+f"(c[3])
        : "r"(a[0]), "r"(a[1]), "r"(a[2]), "r"(a[3]), "r"(b0), "r"(b1));
}
__device__ __forceinline__ void cp16(void* dst_smem, const void* src) {
    uint32_t d = smem_u32(dst_smem);
    asm volatile("cp.async.cg.shared.global [%0], [%1], 16;" :: "r"(d), "l"(src) : "memory");
}
#define CP_COMMIT() asm volatile("cp.async.commit_group;" ::: "memory")
#define CP_WAIT(N)  asm volatile("cp.async.wait_group %0;" :: "n"(N) : "memory")

// ============================================================
// Weight prep: fp32 W[k][n] -> bf16 hi/lo mma fragments in blob order.
// ============================================================
__global__ void prep_kernel(const float* __restrict__ durW,
                            const float* __restrict__ pitW,
                            const float* __restrict__ enW)
{
    int i = blockIdx.x * 256 + threadIdx.x;   // 196608 total
    int lane  = i & 31;
    int nsub  = (i >> 5) & 31;
    int kstep = (i >> 10) & 15;
    int l     = (i >> 14) & 3;
    int p     = i >> 16;                      // 0..2
    const float* W = (p == 0 ? durW : (p == 1 ? pitW : enW)) + l * Hc * Hc;
    int n  = nsub * 8 + (lane >> 2);
    int tg = lane & 3;
    int kA = kstep * 16 + tg * 2;
    int kB = kA + 8;
    float w00 = W[kA * Hc + n],       w01 = W[(kA + 1) * Hc + n];
    float w10 = W[kB * Hc + n],       w11 = W[(kB + 1) * Hc + n];
    float h00 = __bfloat162float(__float2bfloat16(w00));
    float h01 = __bfloat162float(__float2bfloat16(w01));
    float h10 = __bfloat162float(__float2bfloat16(w10));
    float h11 = __bfloat162float(__float2bfloat16(w11));
    uint4 v;
    v.x = pack_bf16x2(h00, h01);
    v.y = pack_bf16x2(h10, h11);
    v.z = pack_bf16x2(w00 - h00, w01 - h01);
    v.w = pack_bf16x2(w10 - h10, w11 - h11);
    g_wblob[i] = v;
}

// ============================================================
// Length regulator: cumsum + searchsorted + masks (1 block / batch)
// ============================================================
__global__ void regulate_kernel(const int* __restrict__ dur,
                                float* __restrict__ out_mellen,
                                float* __restrict__ out_melmask)
{
    __shared__ int cum[Tc];
    const int b = blockIdx.x;
    const int t = threadIdx.x;
    cum[t] = dur[b * Tc + t];
    __syncthreads();
    for (int off = 1; off < Tc; off <<= 1) {
        int v = (t >= off) ? cum[t - off] : 0;
        __syncthreads();
        cum[t] += v;
        __syncthreads();
    }
    const int mel_len = min(cum[Tc - 1], Lc);
    for (int m = t; m < Lc; m += Tc) {
        int lo = 0, hi = Tc;
        while (lo < hi) {
            int mid = (lo + hi) >> 1;
            if (cum[mid] <= m) lo = mid + 1; else hi = mid;
        }
        int idx = min(lo, Tc - 1);
        bool pad = (m >= mel_len);
        g_idx[b * Lc + m]       = idx;
        g_mmask[b * Lc + m]     = pad ? 1 : 0;
        out_melmask[b * Lc + m] = pad ? 1.0f : 0.0f;
    }
    if (t == 0) out_mellen[b] = (float)mel_len;
}

// ============================================================
// mma.sync predictor. 256 threads = 8 warps (2M x 4N), tile 64x256.
// 2 CTAs/SM. SMEM: h_hi/h_lo (pitch 264), 2x16KB B ring, bias, head.
// ============================================================
#define PITCH 264
#define OFF_HHI   0
#define OFF_HLO   (64 * PITCH * 2)                  // 33792
#define OFF_BBUF  (OFF_HLO + 64 * PITCH * 2)        // 67584
#define OFF_BIAS  (OFF_BBUF + 2 * 16384)            // 100352
#define OFF_WHEAD (OFF_BIAS + 4 * 256 * 4)          // 104448
#define OFF_HEAD  (OFF_WHEAD + 256 * 4)             // 105472
#define SMEM_TOTAL (OFF_HEAD + 64 * 4)              // 105728

__global__ void __launch_bounds__(256, 2)
predictor_mma(const float* __restrict__ x,
              const float* __restrict__ src_seq,
              const unsigned char* __restrict__ src_mask,
              const float* __restrict__ dur_b, const float* __restrict__ pit_b,
              const float* __restrict__ en_b,
              const float* __restrict__ dur_w, const float* __restrict__ pit_w,
              const float* __restrict__ en_w,
              const float* __restrict__ dur_b2, const float* __restrict__ pit_b2,
              const float* __restrict__ en_b2,
              float* __restrict__ o_logdur, float* __restrict__ o_pitch,
              float* __restrict__ o_energy)
{
    extern __shared__ char smem[];
    __nv_bfloat16* h_hi = (__nv_bfloat16*)(smem + OFF_HHI);
    __nv_bfloat16* h_lo = (__nv_bfloat16*)(smem + OFF_HLO);
    char*          bbuf = smem + OFF_BBUF;
    float*         bias_s  = (float*)(smem + OFF_BIAS);
    float*         whead_s = (float*)(smem + OFF_WHEAD);
    float*         headsum = (float*)(smem + OFF_HEAD);

    const int tid  = threadIdx.x;
    const int lane = tid & 31;
    const int wid  = tid >> 5;
    const int warpM = wid >> 2;          // 0..1 (32 rows each)
    const int warpN = wid & 3;           // 0..3 (64 cols each)
    const int g  = lane >> 2;
    const int tg = lane & 3;
    const int bid = blockIdx.x;

    int pred;
    long r0;
    const float* bias;
    const float* wh;
    const float* b2;
    float* out;
    if (bid < N_PIT_TILES) {
        pred = 1; r0 = (long)bid * 64;
        bias = pit_b; wh = pit_w; b2 = pit_b2; out = o_pitch;
    } else if (bid < 2 * N_PIT_TILES) {
        pred = 2; r0 = (long)(bid - N_PIT_TILES) * 64;
        bias = en_b; wh = en_w; b2 = en_b2; out = o_energy;
    } else {
        pred = 0; r0 = (long)(bid - 2 * N_PIT_TILES) * 64;
        bias = dur_b; wh = dur_w; b2 = dur_b2; out = o_logdur;
    }
    const char* blob = (const char*)g_wblob + (size_t)pred * 4 * 262144;

    // prefetch chunk 0 (kstep 0 of layer 0): 16KB, 64B per thread
    {
        const char* src = blob + (size_t)tid * 64;
        char* dst = bbuf + tid * 64;
        #pragma unroll
        for (int q = 0; q < 4; q++) cp16(dst + q * 16, src + q * 16);
        CP_COMMIT();
    }

    // bias + head weights + headsum init
    for (int i = tid; i < NLc * Hc; i += 256) bias_s[i] = bias[i];
    if (tid < 256) whead_s[tid] = wh[tid];
    if (tid < 64) headsum[tid] = 0.f;

    // A init: split fp32 input -> bf16 hi/lo in SMEM (gather for pitch/energy)
    {
        const int row = tid >> 2;
        const int c0  = (tid & 3) * 64;
        const long r  = r0 + row;
        const float* xr;
        bool zero = false;
        if (pred == 0) {
            xr = x + r * (long)Hc + c0;
        } else {
            const long b = r / Lc;
            xr = x + ((long)b * Tc + g_idx[r]) * (long)Hc + c0;
            zero = (g_mmask[r] != 0);
        }
        __nv_bfloat16* dh = h_hi + row * PITCH + c0;
        __nv_bfloat16* dl = h_lo + row * PITCH + c0;
        #pragma unroll
        for (int q = 0; q < 16; q++) {
            float4 v = ((const float4*)xr)[q];
            if (zero) v = make_float4(0.f, 0.f, 0.f, 0.f);
            float a0 = __bfloat162float(__float2bfloat16(v.x));
            float a1 = __bfloat162float(__float2bfloat16(v.y));
            float a2 = __bfloat162float(__float2bfloat16(v.z));
            float a3 = __bfloat162float(__float2bfloat16(v.w));
            *(uint32_t*)(dh + q * 4)     = pack_bf16x2(a0, a1);
            *(uint32_t*)(dh + q * 4 + 2) = pack_bf16x2(a2, a3);
            *(uint32_t*)(dl + q * 4)     = pack_bf16x2(v.x - a0, v.y - a1);
            *(uint32_t*)(dl + q * 4 + 2) = pack_bf16x2(v.z - a2, v.w - a3);
        }
    }

    float acc[2][8][4];
    #pragma unroll
    for (int m = 0; m < 2; m++)
        #pragma unroll
        for (int j = 0; j < 8; j++)
            #pragma unroll
            for (int q = 0; q < 4; q++) acc[m][j][q] = 0.f;

    float hp[4] = {0.f, 0.f, 0.f, 0.f};   // head partials

    #pragma unroll 1
    for (int gch = 0; gch < 64; gch++) {
        const int l  = gch >> 4;
        const int ks = gch & 15;

        CP_WAIT(0);          // chunk gch arrived (only group in flight)
        __syncthreads();     // visible to all; everyone done reading gch-1's buffer

        if (gch + 1 < 64) {  // prefetch gch+1 into the buffer gch-1 used (drained)
            const char* src = blob + (size_t)(gch + 1) * 16384 + (size_t)tid * 64;
            char* dst = bbuf + ((gch + 1) & 1) * 16384 + tid * 64;
            #pragma unroll
            for (int q = 0; q < 4; q++) cp16(dst + q * 16, src + q * 16);
            CP_COMMIT();
        }

        const char* bb = bbuf + (gch & 1) * 16384;
        const int k0 = ks * 16;
        uint32_t ahi[2][4], alo[2][4];
        #pragma unroll
        for (int m = 0; m < 2; m++) {
            const int rr = warpM * 32 + m * 16 + g;
            const int ka = k0 + tg * 2;
            ahi[m][0] = *(const uint32_t*)(h_hi + rr * PITCH + ka);
            ahi[m][1] = *(const uint32_t*)(h_hi + (rr + 8) * PITCH + ka);
            ahi[m][2] = *(const uint32_t*)(h_hi + rr * PITCH + ka + 8);
            ahi[m][3] = *(const uint32_t*)(h_hi + (rr + 8) * PITCH + ka + 8);
            alo[m][0] = *(const uint32_t*)(h_lo + rr * PITCH + ka);
            alo[m][1] = *(const uint32_t*)(h_lo + (rr + 8) * PITCH + ka);
            alo[m][2] = *(const uint32_t*)(h_lo + rr * PITCH + ka + 8);
            alo[m][3] = *(const uint32_t*)(h_lo + (rr + 8) * PITCH + ka + 8);
        }
        #pragma unroll
        for (int j = 0; j < 8; j++) {
            const uint4 B = *(const uint4*)(bb +
                ((size_t)(warpN * 8 + j) * 32 + lane) * 16);
            #pragma unroll
            for (int m = 0; m < 2; m++) {
                mma16816(acc[m][j], ahi[m], B.x, B.y);   // Ahi*Bhi
                mma16816(acc[m][j], ahi[m], B.z, B.w);   // Ahi*Blo
                mma16816(acc[m][j], alo[m], B.x, B.y);   // Alo*Bhi
            }
        }

        if (ks == 15) {
            // ---- layer epilogue ----
            const float* bl = bias_s + l * Hc;
            if (l < NLc - 1) {
                __syncthreads();   // all warps done reading A of this layer
                #pragma unroll
                for (int m = 0; m < 2; m++) {
                    const int rr = warpM * 32 + m * 16 + g;
                    #pragma unroll
                    for (int j = 0; j < 8; j++) {
                        const int col = warpN * 64 + j * 8 + tg * 2;
                        float v0 = fmaxf(acc[m][j][0] + bl[col],     0.f);
                        float v1 = fmaxf(acc[m][j][1] + bl[col + 1], 0.f);
                        float v2 = fmaxf(acc[m][j][2] + bl[col],     0.f);
                        float v3 = fmaxf(acc[m][j][3] + bl[col + 1], 0.f);
                        float h0 = __bfloat162float(__float2bfloat16(v0));
                        float h1 = __bfloat162float(__float2bfloat16(v1));
                        float h2 = __bfloat162float(__float2bfloat16(v2));
                        float h3 = __bfloat162float(__float2bfloat16(v3));
                        *(uint32_t*)(h_hi + rr * PITCH + col)       = pack_bf16x2(h0, h1);
                        *(uint32_t*)(h_hi + (rr + 8) * PITCH + col) = pack_bf16x2(h2, h3);
                        *(uint32_t*)(h_lo + rr * PITCH + col)       = pack_bf16x2(v0 - h0, v1 - h1);
                        *(uint32_t*)(h_lo + (rr + 8) * PITCH + col) = pack_bf16x2(v2 - h2, v3 - h3);
                        acc[m][j][0] = 0.f; acc[m][j][1] = 0.f;
                        acc[m][j][2] = 0.f; acc[m][j][3] = 0.f;
                    }
                }
            } else {
                #pragma unroll
                for (int m = 0; m < 2; m++) {
                    #pragma unroll
                    for (int j = 0; j < 8; j++) {
                        const int col = warpN * 64 + j * 8 + tg * 2;
                        float w0 = whead_s[col], w1 = whead_s[col + 1];
                        hp[m * 2]     += fmaxf(acc[m][j][0] + bl[col],     0.f) * w0
                                       + fmaxf(acc[m][j][1] + bl[col + 1], 0.f) * w1;
                        hp[m * 2 + 1] += fmaxf(acc[m][j][2] + bl[col],     0.f) * w0
                                       + fmaxf(acc[m][j][3] + bl[col + 1], 0.f) * w1;
                    }
                }
            }
        }
    }

    // head reduction: atomicAdd into per-row shared slots
    #pragma unroll
    for (int m = 0; m < 2; m++) {
        const int rr = warpM * 32 + m * 16 + g;
        atomicAdd(&headsum[rr],     hp[m * 2]);
        atomicAdd(&headsum[rr + 8], hp[m * 2 + 1]);
    }
    __syncthreads();

    if (tid < 64) {
        const long r = r0 + tid;
        float val = headsum[tid] + b2[0];
        const bool msk = (pred == 0) ? (src_mask[r] != 0) : (g_mmask[r] != 0);
        if (msk) val = 0.f;
        float res;
        if (pred == 0)      res = (tanhf(val) + 1.f) * src_seq[r * 3 + 2];
        else if (pred == 1) res = fmaxf(val, 0.f);
        else                res = val;
        out[r] = res;
    }
}

// ============================================================
// Final: out = gather(x) + pitch_emb[ceil(p*NB)] + energy_emb[ceil(e*NB)]
// ============================================================
__global__ void final_kernel(const float* __restrict__ x,
                             const float* __restrict__ pitch_t,
                             const float* __restrict__ energy_t,
                             const float* __restrict__ pemb,
                             const float* __restrict__ eemb,
                             float* __restrict__ out)
{
    const int total4 = ROWS_MEL * (Hc / 4);
    int e4 = blockIdx.x * blockDim.x + threadIdx.x;
    if (e4 >= total4) return;
    int row = e4 / (Hc / 4);
    int h4  = e4 % (Hc / 4);
    int b   = row / Lc;
    int idx = g_idx[row];
    float4 a = ((const float4*)(x + ((size_t)b * Tc + idx) * Hc))[h4];
    if (g_mmask[row]) a = make_float4(0.f, 0.f, 0.f, 0.f);
    int pi = (int)ceilf(pitch_t[row] * 256.0f);
    int ei = (int)ceilf(energy_t[row] * 256.0f);
    float4 p = ((const float4*)(pemb + (size_t)pi * Hc))[h4];
    float4 q = ((const float4*)(eemb + (size_t)ei * Hc))[h4];
    a.x += p.x + q.x;
    a.y += p.y + q.y;
    a.z += p.z + q.z;
    a.w += p.w + q.w;
    ((float4*)out)[e4] = a;
}

// ============================================================
extern "C" void kernel_launch(void* const* d_in, const int* in_sizes, int n_in,
                              void* d_out, int out_size)
{
    const float* x        = (const float*)d_in[0];   // [B,T,H]
    const float* src_seq  = (const float*)d_in[1];   // [B,T,3]
    const int*   dur_t    = (const int*)  d_in[2];   // [B,T]
    const float* pitch_t  = (const float*)d_in[3];   // [B,L]
    const float* energy_t = (const float*)d_in[4];   // [B,L]
    const unsigned char* src_mask = (const unsigned char*)d_in[5]; // [B,T] bool

    const int base = n_in - 14;
    const float* dur_W  = (const float*)d_in[base + 0];
    const float* dur_b  = (const float*)d_in[base + 1];
    const float* dur_w  = (const float*)d_in[base + 2];
    const float* dur_b2 = (const float*)d_in[base + 3];
    const float* pit_W  = (const float*)d_in[base + 4];
    const float* pit_b  = (const float*)d_in[base + 5];
    const float* pit_w  = (const float*)d_in[base + 6];
    const float* pit_b2 = (const float*)d_in[base + 7];
    const float* en_W   = (const float*)d_in[base + 8];
    const float* en_b   = (const float*)d_in[base + 9];
    const float* en_w   = (const float*)d_in[base + 10];
    const float* en_b2  = (const float*)d_in[base + 11];
    const float* pemb   = (const float*)d_in[base + 12];
    const float* eemb   = (const float*)d_in[base + 13];

    float* out       = (float*)d_out;
    float* o_main    = out;                               // B*L*H
    float* o_logdur  = o_main + (size_t)ROWS_MEL * Hc;    // B*T
    float* o_pitch   = o_logdur + ROWS_DUR;               // B*L
    float* o_energy  = o_pitch + ROWS_MEL;                // B*L
    float* o_mellen  = o_energy + ROWS_MEL;               // B
    float* o_mmask   = o_mellen + Bc;                     // B*L

    cudaFuncSetAttribute(predictor_mma, cudaFuncAttributeMaxDynamicSharedMemorySize, SMEM_TOTAL);

    // 0) build fragment-order weight blob
    prep_kernel<<<768, 256>>>(dur_W, pit_W, en_W);

    // 1) length regulator metadata
    regulate_kernel<<<Bc, Tc>>>(dur_t, o_mellen, o_mmask);

    // 2) all three predictors in one mma.sync kernel (gathers x inline)
    predictor_mma<<<2 * N_PIT_TILES + N_DUR_TILES, 256, SMEM_TOTAL>>>(
        x, src_seq, src_mask,
        dur_b, pit_b, en_b, dur_w, pit_w, en_w, dur_b2, pit_b2, en_b2,
        o_logdur, o_pitch, o_energy);

    // 3) out = gather(x) + pitch_emb + energy_emb
    const int total4 = ROWS_MEL * (Hc / 4);
    final_kernel<<<(total4 + 255) / 256, 256>>>(x, pitch_t, energy_t, pemb, eemb, o_main);
}

// round 6
// speedup vs baseline: 4.4354x; 1.3557x over previous
#include <cuda_runtime.h>
#include <cuda_fp16.h>
#include <cstdint>

// Problem constants
#define Bc   32
#define Tc   512
#define Hc   256
#define Lc   2048
#define NLc  4

static const int ROWS_DUR = Bc * Tc;   // 16384
static const int ROWS_MEL = Bc * Lc;   // 65536
static const int N_PIT_TILES = ROWS_MEL / 64;   // 1024
static const int N_DUR_TILES = ROWS_DUR / 64;   // 256

// Scratch (device globals; no runtime allocation)
__device__ int            g_idx[Bc * Lc];
__device__ unsigned char  g_mmask[Bc * Lc];     // 1 = padded frame
// Fragment-order weight blob (single fp16): [pred(3)][layer(4)][kstep(16)][nsub(32)][lane(32)] uint2
// uint2 = {b(k0,k1) pair, b(k8,k9) pair} fp16x2 for mma.m16n8k16 col-major B frags
__device__ __align__(128) uint2 g_wblob[3 * 4 * 16 * 32 * 32];

__device__ __forceinline__ uint32_t smem_u32(const void* p) {
    uint32_t a;
    asm("{ .reg .u64 t; cvta.to.shared.u64 t, %1; cvt.u32.u64 %0, t; }" : "=r"(a) : "l"(p));
    return a;
}
__device__ __forceinline__ uint32_t pack_h2(float a, float b) {
    __half2 t = __floats2half2_rn(a, b);
    return *reinterpret_cast<uint32_t*>(&t);
}
__device__ __forceinline__ void mma16816(float* c, const uint32_t* a, uint32_t b0, uint32_t b1) {
    asm volatile(
        "mma.sync.aligned.m16n8k16.row.col.f32.f16.f16.f32 "
        "{%0,%1,%2,%3}, {%4,%5,%6,%7}, {%8,%9}, {%0,%1,%2,%3};"
        : "+f"(c[0]), "+f"(c[1]), "+f"(c[2]), "+f"(c[3])
        : "r"(a[0]), "r"(a[1]), "r"(a[2]), "r"(a[3]), "r"(b0), "r"(b1));
}
__device__ __forceinline__ void cp16(void* dst_smem, const void* src) {
    uint32_t d = smem_u32(dst_smem);
    asm volatile("cp.async.cg.shared.global [%0], [%1], 16;" :: "r"(d), "l"(src) : "memory");
}
#define CP_COMMIT() asm volatile("cp.async.commit_group;" ::: "memory")
#define CP_WAIT(N)  asm volatile("cp.async.wait_group %0;" :: "n"(N) : "memory")

// ============================================================
// Weight prep: fp32 W[k][n] -> single fp16 mma fragments in blob order.
// ============================================================
__global__ void prep_kernel(const float* __restrict__ durW,
                            const float* __restrict__ pitW,
                            const float* __restrict__ enW)
{
    int i = blockIdx.x * 256 + threadIdx.x;   // 196608 total
    int lane  = i & 31;
    int nsub  = (i >> 5) & 31;
    int kstep = (i >> 10) & 15;
    int l     = (i >> 14) & 3;
    int p     = i >> 16;                      // 0..2
    const float* W = (p == 0 ? durW : (p == 1 ? pitW : enW)) + l * Hc * Hc;
    int n  = nsub * 8 + (lane >> 2);
    int tg = lane & 3;
    int kA = kstep * 16 + tg * 2;
    int kB = kA + 8;
    uint2 v;
    v.x = pack_h2(W[kA * Hc + n], W[(kA + 1) * Hc + n]);
    v.y = pack_h2(W[kB * Hc + n], W[(kB + 1) * Hc + n]);
    g_wblob[i] = v;
}

// ============================================================
// Length regulator: cumsum + searchsorted + masks (1 block / batch)
// ============================================================
__global__ void regulate_kernel(const int* __restrict__ dur,
                                float* __restrict__ out_mellen,
                                float* __restrict__ out_melmask)
{
    __shared__ int cum[Tc];
    const int b = blockIdx.x;
    const int t = threadIdx.x;
    cum[t] = dur[b * Tc + t];
    __syncthreads();
    for (int off = 1; off < Tc; off <<= 1) {
        int v = (t >= off) ? cum[t - off] : 0;
        __syncthreads();
        cum[t] += v;
        __syncthreads();
    }
    const int mel_len = min(cum[Tc - 1], Lc);
    for (int m = t; m < Lc; m += Tc) {
        int lo = 0, hi = Tc;
        while (lo < hi) {
            int mid = (lo + hi) >> 1;
            if (cum[mid] <= m) lo = mid + 1; else hi = mid;
        }
        int idx = min(lo, Tc - 1);
        bool pad = (m >= mel_len);
        g_idx[b * Lc + m]       = idx;
        g_mmask[b * Lc + m]     = pad ? 1 : 0;
        out_melmask[b * Lc + m] = pad ? 1.0f : 0.0f;
    }
    if (t == 0) out_mellen[b] = (float)mel_len;
}

// ============================================================
// mma.sync predictor. 256 threads = 8 warps (2M x 4N), tile 64x256.
// 2 CTAs/SM. A split fp16 hi/lo (2-term), B single fp16 in 4-deep ring.
// pitch CTAs additionally write o_main (= gather + emb) in their tail.
// ============================================================
#define PITCH 264
#define OFF_HHI   0
#define OFF_HLO   (64 * PITCH * 2)                  // 33792
#define OFF_BBUF  (OFF_HLO + 64 * PITCH * 2)        // 67584
#define OFF_BIAS  (OFF_BBUF + 4 * 8192)             // 100352
#define OFF_WHEAD (OFF_BIAS + 4 * 256 * 4)          // 104448
#define OFF_HEAD  (OFF_WHEAD + 256 * 4)             // 105472
#define SMEM_TOTAL (OFF_HEAD + 64 * 4)              // 105728

__global__ void __launch_bounds__(256, 2)
predictor_mma(const float* __restrict__ x,
              const float* __restrict__ src_seq,
              const unsigned char* __restrict__ src_mask,
              const float* __restrict__ dur_b, const float* __restrict__ pit_b,
              const float* __restrict__ en_b,
              const float* __restrict__ dur_w, const float* __restrict__ pit_w,
              const float* __restrict__ en_w,
              const float* __restrict__ dur_b2, const float* __restrict__ pit_b2,
              const float* __restrict__ en_b2,
              const float* __restrict__ pitch_t, const float* __restrict__ energy_t,
              const float* __restrict__ pemb, const float* __restrict__ eemb,
              float* __restrict__ o_logdur, float* __restrict__ o_pitch,
              float* __restrict__ o_energy, float* __restrict__ o_main)
{
    extern __shared__ char smem[];
    __half* h_hi = (__half*)(smem + OFF_HHI);
    __half* h_lo = (__half*)(smem + OFF_HLO);
    char*   bbuf = smem + OFF_BBUF;
    float*  bias_s  = (float*)(smem + OFF_BIAS);
    float*  whead_s = (float*)(smem + OFF_WHEAD);
    float*  headsum = (float*)(smem + OFF_HEAD);

    const int tid  = threadIdx.x;
    const int lane = tid & 31;
    const int wid  = tid >> 5;
    const int warpM = wid >> 2;          // 0..1 (32 rows each)
    const int warpN = wid & 3;           // 0..3 (64 cols each)
    const int g  = lane >> 2;
    const int tg = lane & 3;
    const int bid = blockIdx.x;

    int pred;
    long r0;
    const float* bias;
    const float* wh;
    const float* b2;
    float* out;
    if (bid < N_PIT_TILES) {
        pred = 1; r0 = (long)bid * 64;
        bias = pit_b; wh = pit_w; b2 = pit_b2; out = o_pitch;
    } else if (bid < 2 * N_PIT_TILES) {
        pred = 2; r0 = (long)(bid - N_PIT_TILES) * 64;
        bias = en_b; wh = en_w; b2 = en_b2; out = o_energy;
    } else {
        pred = 0; r0 = (long)(bid - 2 * N_PIT_TILES) * 64;
        bias = dur_b; wh = dur_w; b2 = dur_b2; out = o_logdur;
    }
    const char* blob = (const char*)g_wblob + (size_t)pred * 4 * 131072;

    // prefetch chunks 0,1,2 (8KB each = 32B per thread) as 3 groups
    #pragma unroll
    for (int c = 0; c < 3; c++) {
        const char* src = blob + c * 8192 + (size_t)tid * 32;
        char* dst = bbuf + c * 8192 + tid * 32;
        cp16(dst, src);
        cp16(dst + 16, src + 16);
        CP_COMMIT();
    }

    // bias + head weights + headsum init
    for (int i = tid; i < NLc * Hc; i += 256) bias_s[i] = bias[i];
    whead_s[tid] = wh[tid];
    if (tid < 64) headsum[tid] = 0.f;

    // A init: split fp32 input -> fp16 hi/lo in SMEM (gather for pitch/energy)
    {
        const int row = tid >> 2;
        const int c0  = (tid & 3) * 64;
        const long r  = r0 + row;
        const float* xr;
        bool zero = false;
        if (pred == 0) {
            xr = x + r * (long)Hc + c0;
        } else {
            const long b = r / Lc;
            xr = x + ((long)b * Tc + g_idx[r]) * (long)Hc + c0;
            zero = (g_mmask[r] != 0);
        }
        __half* dh = h_hi + row * PITCH + c0;
        __half* dl = h_lo + row * PITCH + c0;
        #pragma unroll
        for (int q = 0; q < 16; q++) {
            float4 v = ((const float4*)xr)[q];
            if (zero) v = make_float4(0.f, 0.f, 0.f, 0.f);
            float a0 = __half2float(__float2half_rn(v.x));
            float a1 = __half2float(__float2half_rn(v.y));
            float a2 = __half2float(__float2half_rn(v.z));
            float a3 = __half2float(__float2half_rn(v.w));
            *(uint32_t*)(dh + q * 4)     = pack_h2(a0, a1);
            *(uint32_t*)(dh + q * 4 + 2) = pack_h2(a2, a3);
            *(uint32_t*)(dl + q * 4)     = pack_h2(v.x - a0, v.y - a1);
            *(uint32_t*)(dl + q * 4 + 2) = pack_h2(v.z - a2, v.w - a3);
        }
    }

    float acc[2][8][4];
    #pragma unroll
    for (int m = 0; m < 2; m++)
        #pragma unroll
        for (int j = 0; j < 8; j++)
            #pragma unroll
            for (int q = 0; q < 4; q++) acc[m][j][q] = 0.f;

    float hp[4] = {0.f, 0.f, 0.f, 0.f};   // head partials

    #pragma unroll 1
    for (int gch = 0; gch < 64; gch++) {
        const int l  = gch >> 4;
        const int ks = gch & 15;

        CP_WAIT(2);          // chunk gch arrived (always 3 groups outstanding)
        __syncthreads();     // A/B visibility + WAR protection for slot reuse

        // prefetch gch+3 into slot (gch+3)&3 (drained: == slot of gch-1)
        if (gch + 3 < 64) {
            const char* src = blob + (size_t)(gch + 3) * 8192 + (size_t)tid * 32;
            char* dst = bbuf + ((gch + 3) & 3) * 8192 + tid * 32;
            cp16(dst, src);
            cp16(dst + 16, src + 16);
        }
        CP_COMMIT();         // always commit (possibly empty) to keep count exact

        const char* bb = bbuf + (gch & 3) * 8192;
        const int ka = ks * 16 + tg * 2;
        uint32_t ahi[2][4], alo[2][4];
        #pragma unroll
        for (int m = 0; m < 2; m++) {
            const int rr = warpM * 32 + m * 16 + g;
            ahi[m][0] = *(const uint32_t*)(h_hi + rr * PITCH + ka);
            ahi[m][1] = *(const uint32_t*)(h_hi + (rr + 8) * PITCH + ka);
            ahi[m][2] = *(const uint32_t*)(h_hi + rr * PITCH + ka + 8);
            ahi[m][3] = *(const uint32_t*)(h_hi + (rr + 8) * PITCH + ka + 8);
            alo[m][0] = *(const uint32_t*)(h_lo + rr * PITCH + ka);
            alo[m][1] = *(const uint32_t*)(h_lo + (rr + 8) * PITCH + ka);
            alo[m][2] = *(const uint32_t*)(h_lo + rr * PITCH + ka + 8);
            alo[m][3] = *(const uint32_t*)(h_lo + (rr + 8) * PITCH + ka + 8);
        }
        #pragma unroll
        for (int j = 0; j < 8; j++) {
            const uint2 B = *(const uint2*)(bb +
                ((size_t)(warpN * 8 + j) * 32 + lane) * 8);
            #pragma unroll
            for (int m = 0; m < 2; m++) {
                mma16816(acc[m][j], ahi[m], B.x, B.y);   // Ahi * B
                mma16816(acc[m][j], alo[m], B.x, B.y);   // Alo * B
            }
        }

        if (ks == 15) {
            // ---- layer epilogue ----
            const float* bl = bias_s + l * Hc;
            if (l < NLc - 1) {
                __syncthreads();   // all warps done reading A of this layer
                #pragma unroll
                for (int m = 0; m < 2; m++) {
                    const int rr = warpM * 32 + m * 16 + g;
                    #pragma unroll
                    for (int j = 0; j < 8; j++) {
                        const int col = warpN * 64 + j * 8 + tg * 2;
                        float v0 = fmaxf(acc[m][j][0] + bl[col],     0.f);
                        float v1 = fmaxf(acc[m][j][1] + bl[col + 1], 0.f);
                        float v2 = fmaxf(acc[m][j][2] + bl[col],     0.f);
                        float v3 = fmaxf(acc[m][j][3] + bl[col + 1], 0.f);
                        float h0 = __half2float(__float2half_rn(v0));
                        float h1 = __half2float(__float2half_rn(v1));
                        float h2 = __half2float(__float2half_rn(v2));
                        float h3 = __half2float(__float2half_rn(v3));
                        *(uint32_t*)(h_hi + rr * PITCH + col)       = pack_h2(h0, h1);
                        *(uint32_t*)(h_hi + (rr + 8) * PITCH + col) = pack_h2(h2, h3);
                        *(uint32_t*)(h_lo + rr * PITCH + col)       = pack_h2(v0 - h0, v1 - h1);
                        *(uint32_t*)(h_lo + (rr + 8) * PITCH + col) = pack_h2(v2 - h2, v3 - h3);
                        acc[m][j][0] = 0.f; acc[m][j][1] = 0.f;
                        acc[m][j][2] = 0.f; acc[m][j][3] = 0.f;
                    }
                }
            } else {
                #pragma unroll
                for (int m = 0; m < 2; m++) {
                    #pragma unroll
                    for (int j = 0; j < 8; j++) {
                        const int col = warpN * 64 + j * 8 + tg * 2;
                        float w0 = whead_s[col], w1 = whead_s[col + 1];
                        hp[m * 2]     += fmaxf(acc[m][j][0] + bl[col],     0.f) * w0
                                       + fmaxf(acc[m][j][1] + bl[col + 1], 0.f) * w1;
                        hp[m * 2 + 1] += fmaxf(acc[m][j][2] + bl[col],     0.f) * w0
                                       + fmaxf(acc[m][j][3] + bl[col + 1], 0.f) * w1;
                    }
                }
            }
        }
    }

    // head reduction: atomicAdd into per-row shared slots
    #pragma unroll
    for (int m = 0; m < 2; m++) {
        const int rr = warpM * 32 + m * 16 + g;
        atomicAdd(&headsum[rr],     hp[m * 2]);
        atomicAdd(&headsum[rr + 8], hp[m * 2 + 1]);
    }
    __syncthreads();

    if (tid < 64) {
        const long r = r0 + tid;
        float val = headsum[tid] + b2[0];
        const bool msk = (pred == 0) ? (src_mask[r] != 0) : (g_mmask[r] != 0);
        if (msk) val = 0.f;
        float res;
        if (pred == 0)      res = (tanhf(val) + 1.f) * src_seq[r * 3 + 2];
        else if (pred == 1) res = fmaxf(val, 0.f);
        else                res = val;
        out[r] = res;
    }

    // pitch CTAs also produce o_main = gather(x) + pemb + eemb for their rows
    if (pred == 1) {
        const int row = tid >> 2;
        const int c0  = (tid & 3) * 64;
        const long r  = r0 + row;
        const long b  = r / Lc;
        const float* xr = x + ((long)b * Tc + g_idx[r]) * (long)Hc + c0;
        const bool zero = (g_mmask[r] != 0);
        const int pi = (int)ceilf(pitch_t[r] * 256.0f);
        const int ei = (int)ceilf(energy_t[r] * 256.0f);
        const float4* pe = (const float4*)(pemb + (size_t)pi * Hc + c0);
        const float4* ee = (const float4*)(eemb + (size_t)ei * Hc + c0);
        float4* dst = (float4*)(o_main + r * (long)Hc + c0);
        #pragma unroll
        for (int q = 0; q < 16; q++) {
            float4 a = ((const float4*)xr)[q];
            if (zero) a = make_float4(0.f, 0.f, 0.f, 0.f);
            float4 p = pe[q], e = ee[q];
            float4 tmp;
            tmp.x = a.x + p.x + e.x;
            tmp.y = a.y + p.y + e.y;
            tmp.z = a.z + p.z + e.z;
            tmp.w = a.w + p.w + e.w;
            dst[q] = tmp;
        }
    }
}

// ============================================================
extern "C" void kernel_launch(void* const* d_in, const int* in_sizes, int n_in,
                              void* d_out, int out_size)
{
    const float* x        = (const float*)d_in[0];   // [B,T,H]
    const float* src_seq  = (const float*)d_in[1];   // [B,T,3]
    const int*   dur_t    = (const int*)  d_in[2];   // [B,T]
    const float* pitch_t  = (const float*)d_in[3];   // [B,L]
    const float* energy_t = (const float*)d_in[4];   // [B,L]
    const unsigned char* src_mask = (const unsigned char*)d_in[5]; // [B,T] bool

    const int base = n_in - 14;
    const float* dur_W  = (const float*)d_in[base + 0];
    const float* dur_b  = (const float*)d_in[base + 1];
    const float* dur_w  = (const float*)d_in[base + 2];
    const float* dur_b2 = (const float*)d_in[base + 3];
    const float* pit_W  = (const float*)d_in[base + 4];
    const float* pit_b  = (const float*)d_in[base + 5];
    const float* pit_w  = (const float*)d_in[base + 6];
    const float* pit_b2 = (const float*)d_in[base + 7];
    const float* en_W   = (const float*)d_in[base + 8];
    const float* en_b   = (const float*)d_in[base + 9];
    const float* en_w   = (const float*)d_in[base + 10];
    const float* en_b2  = (const float*)d_in[base + 11];
    const float* pemb   = (const float*)d_in[base + 12];
    const float* eemb   = (const float*)d_in[base + 13];

    float* out       = (float*)d_out;
    float* o_main    = out;                               // B*L*H
    float* o_logdur  = o_main + (size_t)ROWS_MEL * Hc;    // B*T
    float* o_pitch   = o_logdur + ROWS_DUR;               // B*L
    float* o_energy  = o_pitch + ROWS_MEL;                // B*L
    float* o_mellen  = o_energy + ROWS_MEL;               // B
    float* o_mmask   = o_mellen + Bc;                     // B*L

    cudaFuncSetAttribute(predictor_mma, cudaFuncAttributeMaxDynamicSharedMemorySize, SMEM_TOTAL);

    // 0) build fragment-order fp16 weight blob
    prep_kernel<<<768, 256>>>(dur_W, pit_W, en_W);

    // 1) length regulator metadata
    regulate_kernel<<<Bc, Tc>>>(dur_t, o_mellen, o_mmask);

    // 2) predictors + main output in one kernel
    predictor_mma<<<2 * N_PIT_TILES + N_DUR_TILES, 256, SMEM_TOTAL>>>(
        x, src_seq, src_mask,
        dur_b, pit_b, en_b, dur_w, pit_w, en_w, dur_b2, pit_b2, en_b2,
        pitch_t, energy_t, pemb, eemb,
        o_logdur, o_pitch, o_energy, o_main);
}

// round 7
// speedup vs baseline: 6.9623x; 1.5697x over previous
#include <cuda_runtime.h>
#include <cuda_fp16.h>
#include <cstdint>

// Problem constants
#define Bc   32
#define Tc   512
#define Hc   256
#define Lc   2048
#define NLc  4

static const int ROWS_DUR = Bc * Tc;   // 16384
static const int ROWS_MEL = Bc * Lc;   // 65536
static const int N_PIT_TILES = ROWS_MEL / 64;   // 1024
static const int N_DUR_TILES = ROWS_DUR / 64;   // 256

// Scratch (device globals; no runtime allocation)
__device__ int            g_idx[Bc * Lc];
__device__ unsigned char  g_mmask[Bc * Lc];     // 1 = padded frame
// Fragment-order weight blob (single fp16): [pred(3)][layer(4)][kstep(16)][nsub(32)][lane(32)] uint2
// uint2 = {b(k0,k1) pair, b(k8,k9) pair} fp16x2 for mma.m16n8k16 col-major B frags
__device__ __align__(128) uint2 g_wblob[3 * 4 * 16 * 32 * 32];

__device__ __forceinline__ uint32_t smem_u32(const void* p) {
    uint32_t a;
    asm("{ .reg .u64 t; cvta.to.shared.u64 t, %1; cvt.u32.u64 %0, t; }" : "=r"(a) : "l"(p));
    return a;
}
__device__ __forceinline__ uint32_t pack_h2(float a, float b) {
    __half2 t = __floats2half2_rn(a, b);
    return *reinterpret_cast<uint32_t*>(&t);
}
__device__ __forceinline__ void mma16816(float* c, const uint32_t* a, uint32_t b0, uint32_t b1) {
    asm volatile(
        "mma.sync.aligned.m16n8k16.row.col.f32.f16.f16.f32 "
        "{%0,%1,%2,%3}, {%4,%5,%6,%7}, {%8,%9}, {%0,%1,%2,%3};"
        : "+f"(c[0]), "+f"(c[1]), "+f"(c[2]), "+f"(c[3])
        : "r"(a[0]), "r"(a[1]), "r"(a[2]), "r"(a[3]), "r"(b0), "r"(b1));
}
__device__ __forceinline__ void ldmatrix_x4(uint32_t* r, uint32_t smem_addr) {
    asm volatile("ldmatrix.sync.aligned.m8n8.x4.shared.b16 {%0,%1,%2,%3}, [%4];"
        : "=r"(r[0]), "=r"(r[1]), "=r"(r[2]), "=r"(r[3]) : "r"(smem_addr));
}
__device__ __forceinline__ void cp16(void* dst_smem, const void* src) {
    uint32_t d = smem_u32(dst_smem);
    asm volatile("cp.async.cg.shared.global [%0], [%1], 16;" :: "r"(d), "l"(src) : "memory");
}
#define CP_COMMIT() asm volatile("cp.async.commit_group;" ::: "memory")
#define CP_WAIT(N)  asm volatile("cp.async.wait_group %0;" :: "n"(N) : "memory")

// ============================================================
// Weight prep: fp32 W[k][n] -> single fp16 mma fragments in blob order.
// ============================================================
__global__ void prep_kernel(const float* __restrict__ durW,
                            const float* __restrict__ pitW,
                            const float* __restrict__ enW)
{
    int i = blockIdx.x * 256 + threadIdx.x;   // 196608 total
    int lane  = i & 31;
    int nsub  = (i >> 5) & 31;
    int kstep = (i >> 10) & 15;
    int l     = (i >> 14) & 3;
    int p     = i >> 16;                      // 0..2
    const float* W = (p == 0 ? durW : (p == 1 ? pitW : enW)) + l * Hc * Hc;
    int n  = nsub * 8 + (lane >> 2);
    int tg = lane & 3;
    int kA = kstep * 16 + tg * 2;
    int kB = kA + 8;
    uint2 v;
    v.x = pack_h2(W[kA * Hc + n], W[(kA + 1) * Hc + n]);
    v.y = pack_h2(W[kB * Hc + n], W[(kB + 1) * Hc + n]);
    g_wblob[i] = v;
}

// ============================================================
// Length regulator: cumsum + searchsorted + masks (1 block / batch)
// ============================================================
__global__ void regulate_kernel(const int* __restrict__ dur,
                                float* __restrict__ out_mellen,
                                float* __restrict__ out_melmask)
{
    __shared__ int cum[Tc];
    const int b = blockIdx.x;
    const int t = threadIdx.x;
    cum[t] = dur[b * Tc + t];
    __syncthreads();
    for (int off = 1; off < Tc; off <<= 1) {
        int v = (t >= off) ? cum[t - off] : 0;
        __syncthreads();
        cum[t] += v;
        __syncthreads();
    }
    const int mel_len = min(cum[Tc - 1], Lc);
    for (int m = t; m < Lc; m += Tc) {
        int lo = 0, hi = Tc;
        while (lo < hi) {
            int mid = (lo + hi) >> 1;
            if (cum[mid] <= m) lo = mid + 1; else hi = mid;
        }
        int idx = min(lo, Tc - 1);
        bool pad = (m >= mel_len);
        g_idx[b * Lc + m]       = idx;
        g_mmask[b * Lc + m]     = pad ? 1 : 0;
        out_melmask[b * Lc + m] = pad ? 1.0f : 0.0f;
    }
    if (t == 0) out_mellen[b] = (float)mel_len;
}

// ============================================================
// mma.sync predictor. 256 threads = 8 warps (2M x 4N), tile 64x256.
// 2 CTAs/SM. Single fp16 A (ldmatrix) and B (4-deep cp.async ring).
// pitch CTAs additionally write o_main (= gather + emb) in their tail.
// ============================================================
#define PITCH 264
#define OFF_HHI   0
#define OFF_BBUF  (64 * PITCH * 2)                  // 33792
#define OFF_BIAS  (OFF_BBUF + 4 * 8192)             // 66560
#define OFF_WHEAD (OFF_BIAS + 4 * 256 * 4)          // 70656
#define OFF_HEAD  (OFF_WHEAD + 256 * 4)             // 71680
#define SMEM_TOTAL (OFF_HEAD + 64 * 4)              // 71936

__global__ void __launch_bounds__(256, 2)
predictor_mma(const float* __restrict__ x,
              const float* __restrict__ src_seq,
              const unsigned char* __restrict__ src_mask,
              const float* __restrict__ dur_b, const float* __restrict__ pit_b,
              const float* __restrict__ en_b,
              const float* __restrict__ dur_w, const float* __restrict__ pit_w,
              const float* __restrict__ en_w,
              const float* __restrict__ dur_b2, const float* __restrict__ pit_b2,
              const float* __restrict__ en_b2,
              const float* __restrict__ pitch_t, const float* __restrict__ energy_t,
              const float* __restrict__ pemb, const float* __restrict__ eemb,
              float* __restrict__ o_logdur, float* __restrict__ o_pitch,
              float* __restrict__ o_energy, float* __restrict__ o_main)
{
    extern __shared__ char smem[];
    __half* h_hi = (__half*)(smem + OFF_HHI);
    char*   bbuf = smem + OFF_BBUF;
    float*  bias_s  = (float*)(smem + OFF_BIAS);
    float*  whead_s = (float*)(smem + OFF_WHEAD);
    float*  headsum = (float*)(smem + OFF_HEAD);

    const int tid  = threadIdx.x;
    const int lane = tid & 31;
    const int wid  = tid >> 5;
    const int warpM = wid >> 2;          // 0..1 (32 rows each)
    const int warpN = wid & 3;           // 0..3 (64 cols each)
    const int g  = lane >> 2;
    const int tg = lane & 3;
    const int bid = blockIdx.x;

    int pred;
    long r0;
    const float* bias;
    const float* wh;
    const float* b2;
    float* out;
    if (bid < N_PIT_TILES) {
        pred = 1; r0 = (long)bid * 64;
        bias = pit_b; wh = pit_w; b2 = pit_b2; out = o_pitch;
    } else if (bid < 2 * N_PIT_TILES) {
        pred = 2; r0 = (long)(bid - N_PIT_TILES) * 64;
        bias = en_b; wh = en_w; b2 = en_b2; out = o_energy;
    } else {
        pred = 0; r0 = (long)(bid - 2 * N_PIT_TILES) * 64;
        bias = dur_b; wh = dur_w; b2 = dur_b2; out = o_logdur;
    }
    const char* blob = (const char*)g_wblob + (size_t)pred * 4 * 131072;

    // prefetch chunks 0,1,2 (8KB each = 32B per thread) as 3 groups
    #pragma unroll
    for (int c = 0; c < 3; c++) {
        const char* src = blob + c * 8192 + (size_t)tid * 32;
        char* dst = bbuf + c * 8192 + tid * 32;
        cp16(dst, src);
        cp16(dst + 16, src + 16);
        CP_COMMIT();
    }

    // bias + head weights + headsum init
    for (int i = tid; i < NLc * Hc; i += 256) bias_s[i] = bias[i];
    whead_s[tid] = wh[tid];
    if (tid < 64) headsum[tid] = 0.f;

    // A init: fp32 input -> fp16 in SMEM (gather for pitch/energy)
    {
        const int row = tid >> 2;
        const int c0  = (tid & 3) * 64;
        const long r  = r0 + row;
        const float* xr;
        bool zero = false;
        if (pred == 0) {
            xr = x + r * (long)Hc + c0;
        } else {
            const long b = r / Lc;
            xr = x + ((long)b * Tc + g_idx[r]) * (long)Hc + c0;
            zero = (g_mmask[r] != 0);
        }
        __half* dh = h_hi + row * PITCH + c0;
        #pragma unroll
        for (int q = 0; q < 16; q++) {
            float4 v = ((const float4*)xr)[q];
            if (zero) v = make_float4(0.f, 0.f, 0.f, 0.f);
            *(uint32_t*)(dh + q * 4)     = pack_h2(v.x, v.y);
            *(uint32_t*)(dh + q * 4 + 2) = pack_h2(v.z, v.w);
        }
    }

    // per-warp ldmatrix base addresses (bytes), one per m-subtile
    const uint32_t hbase = smem_u32(h_hi);
    uint32_t a_addr[2];
    #pragma unroll
    for (int m = 0; m < 2; m++) {
        const int rr = warpM * 32 + m * 16 + (lane & 15);
        a_addr[m] = hbase + (uint32_t)(rr * PITCH + (lane >> 4) * 8) * 2;
    }

    float acc[2][8][4];
    #pragma unroll
    for (int m = 0; m < 2; m++)
        #pragma unroll
        for (int j = 0; j < 8; j++)
            #pragma unroll
            for (int q = 0; q < 4; q++) acc[m][j][q] = 0.f;

    float hp[4] = {0.f, 0.f, 0.f, 0.f};   // head partials

    #pragma unroll 1
    for (int gch = 0; gch < 64; gch++) {
        const int l  = gch >> 4;
        const int ks = gch & 15;

        CP_WAIT(2);          // chunk gch arrived (always 3 groups outstanding)
        __syncthreads();     // A/B visibility + WAR protection for slot reuse

        // prefetch gch+3 into slot (gch+3)&3 (drained: == slot of gch-1)
        if (gch + 3 < 64) {
            const char* src = blob + (size_t)(gch + 3) * 8192 + (size_t)tid * 32;
            char* dst = bbuf + ((gch + 3) & 3) * 8192 + tid * 32;
            cp16(dst, src);
            cp16(dst + 16, src + 16);
        }
        CP_COMMIT();         // always commit (possibly empty) to keep count exact

        const char* bb = bbuf + (gch & 3) * 8192;
        uint32_t a[2][4];
        ldmatrix_x4(a[0], a_addr[0] + ks * 32);
        ldmatrix_x4(a[1], a_addr[1] + ks * 32);

        #pragma unroll
        for (int j = 0; j < 8; j++) {
            const uint2 B = *(const uint2*)(bb +
                ((size_t)(warpN * 8 + j) * 32 + lane) * 8);
            mma16816(acc[0][j], a[0], B.x, B.y);
            mma16816(acc[1][j], a[1], B.x, B.y);
        }

        if (ks == 15) {
            // ---- layer epilogue ----
            const float* bl = bias_s + l * Hc;
            if (l < NLc - 1) {
                __syncthreads();   // all warps done reading A of this layer
                #pragma unroll
                for (int m = 0; m < 2; m++) {
                    const int rr = warpM * 32 + m * 16 + g;
                    #pragma unroll
                    for (int j = 0; j < 8; j++) {
                        const int col = warpN * 64 + j * 8 + tg * 2;
                        float v0 = fmaxf(acc[m][j][0] + bl[col],     0.f);
                        float v1 = fmaxf(acc[m][j][1] + bl[col + 1], 0.f);
                        float v2 = fmaxf(acc[m][j][2] + bl[col],     0.f);
                        float v3 = fmaxf(acc[m][j][3] + bl[col + 1], 0.f);
                        *(uint32_t*)(h_hi + rr * PITCH + col)       = pack_h2(v0, v1);
                        *(uint32_t*)(h_hi + (rr + 8) * PITCH + col) = pack_h2(v2, v3);
                        acc[m][j][0] = 0.f; acc[m][j][1] = 0.f;
                        acc[m][j][2] = 0.f; acc[m][j][3] = 0.f;
                    }
                }
            } else {
                #pragma unroll
                for (int m = 0; m < 2; m++) {
                    #pragma unroll
                    for (int j = 0; j < 8; j++) {
                        const int col = warpN * 64 + j * 8 + tg * 2;
                        float w0 = whead_s[col], w1 = whead_s[col + 1];
                        hp[m * 2]     += fmaxf(acc[m][j][0] + bl[col],     0.f) * w0
                                       + fmaxf(acc[m][j][1] + bl[col + 1], 0.f) * w1;
                        hp[m * 2 + 1] += fmaxf(acc[m][j][2] + bl[col],     0.f) * w0
                                       + fmaxf(acc[m][j][3] + bl[col + 1], 0.f) * w1;
                    }
                }
            }
        }
    }

    // head reduction: atomicAdd into per-row shared slots
    #pragma unroll
    for (int m = 0; m < 2; m++) {
        const int rr = warpM * 32 + m * 16 + g;
        atomicAdd(&headsum[rr],     hp[m * 2]);
        atomicAdd(&headsum[rr + 8], hp[m * 2 + 1]);
    }
    __syncthreads();

    if (tid < 64) {
        const long r = r0 + tid;
        float val = headsum[tid] + b2[0];
        const bool msk = (pred == 0) ? (src_mask[r] != 0) : (g_mmask[r] != 0);
        if (msk) val = 0.f;
        float res;
        if (pred == 0)      res = (tanhf(val) + 1.f) * src_seq[r * 3 + 2];
        else if (pred == 1) res = fmaxf(val, 0.f);
        else                res = val;
        out[r] = res;
    }

    // pitch CTAs also produce o_main = gather(x) + pemb + eemb for their rows
    if (pred == 1) {
        const int row = tid >> 2;
        const int c0  = (tid & 3) * 64;
        const long r  = r0 + row;
        const long b  = r / Lc;
        const float* xr = x + ((long)b * Tc + g_idx[r]) * (long)Hc + c0;
        const bool zero = (g_mmask[r] != 0);
        const int pi = (int)ceilf(pitch_t[r] * 256.0f);
        const int ei = (int)ceilf(energy_t[r] * 256.0f);
        const float4* pe = (const float4*)(pemb + (size_t)pi * Hc + c0);
        const float4* ee = (const float4*)(eemb + (size_t)ei * Hc + c0);
        float4* dst = (float4*)(o_main + r * (long)Hc + c0);
        #pragma unroll
        for (int q = 0; q < 16; q++) {
            float4 a = ((const float4*)xr)[q];
            if (zero) a = make_float4(0.f, 0.f, 0.f, 0.f);
            float4 p = pe[q], e = ee[q];
            float4 tmp;
            tmp.x = a.x + p.x + e.x;
            tmp.y = a.y + p.y + e.y;
            tmp.z = a.z + p.z + e.z;
            tmp.w = a.w + p.w + e.w;
            dst[q] = tmp;
        }
    }
}

// ============================================================
extern "C" void kernel_launch(void* const* d_in, const int* in_sizes, int n_in,
                              void* d_out, int out_size)
{
    const float* x        = (const float*)d_in[0];   // [B,T,H]
    const float* src_seq  = (const float*)d_in[1];   // [B,T,3]
    const int*   dur_t    = (const int*)  d_in[2];   // [B,T]
    const float* pitch_t  = (const float*)d_in[3];   // [B,L]
    const float* energy_t = (const float*)d_in[4];   // [B,L]
    const unsigned char* src_mask = (const unsigned char*)d_in[5]; // [B,T] bool

    const int base = n_in - 14;
    const float* dur_W  = (const float*)d_in[base + 0];
    const float* dur_b  = (const float*)d_in[base + 1];
    const float* dur_w  = (const float*)d_in[base + 2];
    const float* dur_b2 = (const float*)d_in[base + 3];
    const float* pit_W  = (const float*)d_in[base + 4];
    const float* pit_b  = (const float*)d_in[base + 5];
    const float* pit_w  = (const float*)d_in[base + 6];
    const float* pit_b2 = (const float*)d_in[base + 7];
    const float* en_W   = (const float*)d_in[base + 8];
    const float* en_b   = (const float*)d_in[base + 9];
    const float* en_w   = (const float*)d_in[base + 10];
    const float* en_b2  = (const float*)d_in[base + 11];
    const float* pemb   = (const float*)d_in[base + 12];
    const float* eemb   = (const float*)d_in[base + 13];

    float* out       = (float*)d_out;
    float* o_main    = out;                               // B*L*H
    float* o_logdur  = o_main + (size_t)ROWS_MEL * Hc;    // B*T
    float* o_pitch   = o_logdur + ROWS_DUR;               // B*L
    float* o_energy  = o_pitch + ROWS_MEL;                // B*L
    float* o_mellen  = o_energy + ROWS_MEL;               // B
    float* o_mmask   = o_mellen + Bc;                     // B*L

    cudaFuncSetAttribute(predictor_mma, cudaFuncAttributeMaxDynamicSharedMemorySize, SMEM_TOTAL);

    // 0) build fragment-order fp16 weight blob
    prep_kernel<<<768, 256>>>(dur_W, pit_W, en_W);

    // 1) length regulator metadata
    regulate_kernel<<<Bc, Tc>>>(dur_t, o_mellen, o_mmask);

    // 2) predictors + main output in one kernel
    predictor_mma<<<2 * N_PIT_TILES + N_DUR_TILES, 256, SMEM_TOTAL>>>(
        x, src_seq, src_mask,
        dur_b, pit_b, en_b, dur_w, pit_w, en_w, dur_b2, pit_b2, en_b2,
        pitch_t, energy_t, pemb, eemb,
        o_logdur, o_pitch, o_energy, o_main);
}